// round 1
// baseline (speedup 1.0000x reference)
#include <cuda_runtime.h>

#define H_IMG 512
#define W_IMG 512
#define NPLANES 96            // 32 * 3
#define TW 32
#define TH 32
#define IW 42                 // TW + 10
#define IH 42                 // TH + 10
#define SS 43                 // input smem row stride (odd -> conflict-free)
#define MS 33                 // intermediate smem row stride
#define NT 256
#define C1F 6.5025f
#define C2F 58.5225f
#define NPIX 25165824.0       // 32*3*512*512

__device__ double g_accum;

__global__ void zero_accum_kernel() { g_accum = 0.0; }

__global__ void __launch_bounds__(NT) ssim_main(const float* __restrict__ gen,
                                                const float* __restrict__ ref) {
    __shared__ float sg[IH * SS];
    __shared__ float sr[IH * SS];
    __shared__ float m1[IH * MS];
    __shared__ float m2[IH * MS];
    __shared__ float mgg[IH * MS];
    __shared__ float mrr[IH * MS];
    __shared__ float mgr[IH * MS];
    __shared__ float wsum[8];

    // Normalized 1D Gaussian, sigma=1.5, ws=11 (symmetric)
    const float W11[11] = {0.00102838f, 0.00759871f, 0.03600077f, 0.10936070f,
                           0.21300560f, 0.26601180f, 0.21300560f, 0.10936070f,
                           0.03600077f, 0.00759871f, 0.00102838f};

    const int tid = threadIdx.x;
    const int x0 = blockIdx.x * TW;
    const int y0 = blockIdx.y * TH;
    const size_t pb = (size_t)blockIdx.z * (size_t)(H_IMG * W_IMG);
    const float* gp = gen + pb;
    const float* rp = ref + pb;

    // ---- Stage 0: load input tile with halo, scale to [0,1], zero-pad ----
    for (int i = tid; i < IH * IW; i += NT) {
        int r = i / IW;
        int c = i - r * IW;
        int gy = y0 + r - 5;
        int gx = x0 + c - 5;
        float gv = 0.f, rv = 0.f;
        if ((unsigned)gy < (unsigned)H_IMG && (unsigned)gx < (unsigned)W_IMG) {
            int idx = gy * W_IMG + gx;
            gv = fmaf(gp[idx], 0.5f, 0.5f);
            rv = fmaf(rp[idx], 0.5f, 0.5f);
        }
        sg[r * SS + c] = gv;
        sr[r * SS + c] = rv;
    }
    __syncthreads();

    // ---- Stage 1: horizontal conv of 5 fields, 4 output cols per item ----
    // items: 42 rows x 8 col-chunks = 336
    for (int item = tid; item < IH * 8; item += NT) {
        int r = item >> 3;
        int c0 = (item & 7) << 2;
        const float* sgr = sg + r * SS + c0;
        const float* srr = sr + r * SS + c0;
        float gv[14], rv[14], gg[14], rr[14], gr[14];
#pragma unroll
        for (int t = 0; t < 14; t++) {
            float a = sgr[t];
            float b = srr[t];
            gv[t] = a; rv[t] = b;
            gg[t] = a * a; rr[t] = b * b; gr[t] = a * b;
        }
        float a1[4]  = {0.f, 0.f, 0.f, 0.f};
        float a2[4]  = {0.f, 0.f, 0.f, 0.f};
        float agg[4] = {0.f, 0.f, 0.f, 0.f};
        float arr[4] = {0.f, 0.f, 0.f, 0.f};
        float agr[4] = {0.f, 0.f, 0.f, 0.f};
#pragma unroll
        for (int k = 0; k < 11; k++) {
            float wk = W11[k];
#pragma unroll
            for (int j = 0; j < 4; j++) {
                a1[j]  = fmaf(wk, gv[k + j], a1[j]);
                a2[j]  = fmaf(wk, rv[k + j], a2[j]);
                agg[j] = fmaf(wk, gg[k + j], agg[j]);
                arr[j] = fmaf(wk, rr[k + j], arr[j]);
                agr[j] = fmaf(wk, gr[k + j], agr[j]);
            }
        }
        int o = r * MS + c0;
#pragma unroll
        for (int j = 0; j < 4; j++) {
            m1[o + j]  = a1[j];
            m2[o + j]  = a2[j];
            mgg[o + j] = agg[j];
            mrr[o + j] = arr[j];
            mgr[o + j] = agr[j];
        }
    }
    __syncthreads();

    // ---- Stage 2: vertical conv (4 output rows per thread) + SSIM ----
    float lsum = 0.f;
    {
        const int c = tid & 31;
        const int r0 = (tid >> 5) << 2;   // 8 groups * 4 rows = 32

        float o1[4], o2[4], ogg[4], orr[4], ogr[4];

        // one field at a time to bound register pressure
#define VCONV(MARR, OUT)                                              \
        {                                                             \
            float v[14];                                              \
            _Pragma("unroll")                                         \
            for (int t = 0; t < 14; t++) v[t] = MARR[(r0 + t) * MS + c]; \
            _Pragma("unroll")                                         \
            for (int j = 0; j < 4; j++) {                             \
                float acc = 0.f;                                      \
                _Pragma("unroll")                                     \
                for (int k = 0; k < 11; k++)                          \
                    acc = fmaf(W11[k], v[j + k], acc);                \
                OUT[j] = acc;                                         \
            }                                                         \
        }
        VCONV(m1,  o1)
        VCONV(m2,  o2)
        VCONV(mgg, ogg)
        VCONV(mrr, orr)
        VCONV(mgr, ogr)
#undef VCONV

#pragma unroll
        for (int j = 0; j < 4; j++) {
            float mu1 = o1[j], mu2 = o2[j];
            float mu1s = mu1 * mu1;
            float mu2s = mu2 * mu2;
            float mu12 = mu1 * mu2;
            float s11 = ogg[j] - mu1s;
            float s22 = orr[j] - mu2s;
            float s12 = ogr[j] - mu12;
            float num = (2.f * mu12 + C1F) * (2.f * s12 + C2F);
            float den = (mu1s + mu2s + C1F) * (s11 + s22 + C2F);
            lsum += num / den;
        }
    }

    // ---- Block reduction (fp32) + global double atomic ----
#pragma unroll
    for (int off = 16; off > 0; off >>= 1)
        lsum += __shfl_xor_sync(0xffffffffu, lsum, off);
    if ((tid & 31) == 0) wsum[tid >> 5] = lsum;
    __syncthreads();
    if (tid == 0) {
        float s = 0.f;
#pragma unroll
        for (int i = 0; i < 8; i++) s += wsum[i];
        atomicAdd(&g_accum, (double)s);
    }
}

__global__ void finalize_kernel(float* __restrict__ out) {
    out[0] = (float)(1.0 - g_accum / NPIX);
}

extern "C" void kernel_launch(void* const* d_in, const int* in_sizes, int n_in,
                              void* d_out, int out_size) {
    const float* gen = (const float*)d_in[0];
    const float* ref = (const float*)d_in[1];
    float* out = (float*)d_out;

    zero_accum_kernel<<<1, 1>>>();
    dim3 grid(W_IMG / TW, H_IMG / TH, NPLANES);
    ssim_main<<<grid, NT>>>(gen, ref);
    finalize_kernel<<<1, 1>>>(out);
}